// round 16
// baseline (speedup 1.0000x reference)
#include <cuda_runtime.h>

// Problem constants
#define B_  4
#define C_  32
#define H_  720
#define W_  720
#define HW_ (H_ * W_)      // 518400
#define HW4_ (HW_ / 4)     // 129600
#define W4_ (W_ / 4)       // 180
#define PAD_ 4

#define CHANSUM_BLOCKS ((B_ * HW4_ + 255) / 256)   // 2025 (exact)

// Scratch: channel sum (pre-divided by 9). 8.3 MB -> L2-resident.
__device__ float g_s[B_ * HW_];
__device__ float g_W2[C_ * 3];   // W2[o,kh] = sum_c conv_w[o,c,kh,0]

// ---------------------------------------------------------------------------
// Kernel 1: s[b,h,w] = (1/9) * sum_c x[b,c,h,w].  float4 streaming, 265 MB read.
// __ldcs: x is read exactly once; don't let it evict s from L2.
// The LAST block (index CHANSUM_BLOCKS) instead collapses conv_w over input
// channels into g_W2 — piggybacked so no separate launch is serialized.
// ---------------------------------------------------------------------------
__global__ void chansum_kernel(const float* __restrict__ x,
                               const float* __restrict__ conv_w) {
    if (blockIdx.x == CHANSUM_BLOCKS) {
        int t = threadIdx.x;          // t = o*3 + kh, 0..95
        if (t < C_ * 3) {
            int o = t / 3;
            int kh = t - o * 3;
            float acc = 0.f;
            #pragma unroll
            for (int c = 0; c < C_; ++c)
                acc += conv_w[o * (C_ * 3) + c * 3 + kh];
            g_W2[t] = acc;
        }
        return;
    }

    int idx = blockIdx.x * blockDim.x + threadIdx.x;   // 0 .. B*HW4-1
    int b = idx / HW4_;
    int p = idx - b * HW4_;

    const float4* x4 = reinterpret_cast<const float4*>(x);
    const float4* base = x4 + (long long)b * C_ * HW4_ + p;

    float4 acc = make_float4(0.f, 0.f, 0.f, 0.f);
    #pragma unroll
    for (int c = 0; c < C_; ++c) {
        float4 v = __ldcs(base + (long long)c * HW4_);
        acc.x += v.x; acc.y += v.y; acc.z += v.z; acc.w += v.w;
    }
    const float inv9 = 1.0f / 9.0f;
    acc.x *= inv9; acc.y *= inv9; acc.z *= inv9; acc.w *= inv9;
    reinterpret_cast<float4*>(g_s)[idx] = acc;
}

// ---------------------------------------------------------------------------
// Kernel 2 (fused, multi-row): per block (b, h0..h0+3):
//   - stage s rows h0-5 .. h0+8 (14 rows), logical cols -4..723, into smem
//   - compute 6 shared diagonal rows  acc[dr] = D(h0-1+dr, .), dr = 0..5,
//     where D(h',w) = sum_{δ=-4..4} s[h'+δ, w+δ]  (zero outside the image)
//   - zero D rows whose h' is outside [0,H)  (conv zero padding in H)
//   - out[b,o,h0+hh,w] = W2[o,0]*acc[hh] + W2[o,1]*acc[hh+1] + W2[o,2]*acc[hh+2]
//
// Smem row stride 728 floats; cols 0..3 and 724..727 are permanent zeros.
// Each thread owns 4 w's; per staged row it reads 3 aligned float4 (12 floats
// covering every (j, δ) combination) -> conflict-free LDS.128, static adds.
// Staged row r holds s[h0-5+r]; for D row dr the tap at row r is at local
// column j + (r - dr), valid for r in [dr, dr+8].
// ---------------------------------------------------------------------------
#define SROW_ 728
#define NH_ 4
#define NROWS_ 14            // NH_ + 10 staged rows
__global__ __launch_bounds__(192, 5) void fused_epilogue_kernel(float* __restrict__ out) {
    __shared__ float S[NROWS_ * SROW_];     // 40,768 B
    __shared__ float sw2[C_ * 3];

    int tid = threadIdx.x;              // 0..191
    int h0 = blockIdx.x * NH_;          // 0,4,...,716
    int b = blockIdx.y;                 // 0..3

    if (tid < C_ * 3) sw2[tid] = g_W2[tid];   // single coalesced 384B load

    // zero the 8 edge columns of each of the 14 rows
    if (tid >= 96 && tid < 96 + NROWS_) {
        int r = tid - 96;
        #pragma unroll
        for (int e = 0; e < 4; ++e) {
            S[r * SROW_ + e] = 0.f;
            S[r * SROW_ + 724 + e] = 0.f;
        }
    }

    // stage 14 rows: smem col 4+4k <- global col 4k (float4, 16B-aligned)
    const float4* s4 = reinterpret_cast<const float4*>(g_s);
    if (tid < W4_) {
        #pragma unroll
        for (int r = 0; r < NROWS_; ++r) {
            int row = h0 - 5 + r;
            float4 v = make_float4(0.f, 0.f, 0.f, 0.f);
            if ((unsigned)row < (unsigned)H_)
                v = s4[(long long)b * HW4_ + (long long)row * W4_ + tid];
            *reinterpret_cast<float4*>(&S[r * SROW_ + 4 + 4 * tid]) = v;
        }
    }
    __syncthreads();

    if (tid >= W4_) return;

    // accumulate the 6 diagonal rows D(h0-1 .. h0+4)
    float acc[6][4];
    #pragma unroll
    for (int dr = 0; dr < 6; ++dr)
        #pragma unroll
        for (int j = 0; j < 4; ++j)
            acc[dr][j] = 0.f;

    #pragma unroll
    for (int r = 0; r < NROWS_; ++r) {
        const float* rowp = &S[r * SROW_ + 4 * tid];
        float4 v0 = *reinterpret_cast<const float4*>(rowp + 0);
        float4 v1 = *reinterpret_cast<const float4*>(rowp + 4);
        float4 v2 = *reinterpret_cast<const float4*>(rowp + 8);
        float v[12] = {v0.x, v0.y, v0.z, v0.w,
                       v1.x, v1.y, v1.z, v1.w,
                       v2.x, v2.y, v2.z, v2.w};
        #pragma unroll
        for (int dr = 0; dr < 6; ++dr) {
            if (r >= dr && r <= dr + 8) {
                #pragma unroll
                for (int j = 0; j < 4; ++j)
                    acc[dr][j] += v[j + r - dr];
            }
        }
    }

    // conv zero-padding in H: D rows outside the image are the conv's zero pad
    #pragma unroll
    for (int dr = 0; dr < 6; ++dr) {
        int hp = h0 - 1 + dr;
        if (hp < 0 || hp >= H_) {
            acc[dr][0] = acc[dr][1] = acc[dr][2] = acc[dr][3] = 0.f;
        }
    }

    float4* out4 = reinterpret_cast<float4*>(out);
    #pragma unroll 4
    for (int o = 0; o < C_; ++o) {
        float w0 = sw2[o * 3 + 0];
        float w1 = sw2[o * 3 + 1];
        float w2 = sw2[o * 3 + 2];
        long long obase = ((long long)(b * C_ + o) * H_ + h0) * W4_ + tid;
        #pragma unroll
        for (int hh = 0; hh < NH_; ++hh) {
            float4 rr;
            rr.x = w0 * acc[hh][0] + w1 * acc[hh + 1][0] + w2 * acc[hh + 2][0];
            rr.y = w0 * acc[hh][1] + w1 * acc[hh + 1][1] + w2 * acc[hh + 2][1];
            rr.z = w0 * acc[hh][2] + w1 * acc[hh + 1][2] + w2 * acc[hh + 2][2];
            rr.w = w0 * acc[hh][3] + w1 * acc[hh + 1][3] + w2 * acc[hh + 2][3];
            __stcs(&out4[obase + (long long)hh * W4_], rr);
        }
    }
}

// ---------------------------------------------------------------------------
extern "C" void kernel_launch(void* const* d_in, const int* in_sizes, int n_in,
                              void* d_out, int out_size) {
    const float* x      = (const float*)d_in[0];   // [4,32,720,720] f32
    const float* conv_w = (const float*)d_in[1];   // [32,32,3,1] f32
    float* out          = (float*)d_out;           // [4,32,720,720] f32

    (void)in_sizes; (void)n_in; (void)out_size;

    // +1 block: the extra block computes g_W2 from conv_w
    chansum_kernel<<<CHANSUM_BLOCKS + 1, 256>>>(x, conv_w);

    {
        dim3 grid(H_ / NH_, B_);                    // 180 x 4 = 720 blocks
        fused_epilogue_kernel<<<grid, 192>>>(out);
    }
}